// round 1
// baseline (speedup 1.0000x reference)
#include <cuda_runtime.h>
#include <cuda_bf16.h>

#define N_NODES 50000
#define FEAT 128

// ---------------- scratch (static device globals; no allocation) ----------------
__device__ __align__(16) float g_buf0[(size_t)N_NODES * FEAT];
__device__ __align__(16) float g_buf1[(size_t)N_NODES * FEAT];
__device__ float g_rs_out[N_NODES];
__device__ float g_rs_in[N_NODES];
__device__ int   g_deg_out[N_NODES];
__device__ int   g_deg_in[N_NODES];

// ---------------- degree kernels ----------------
__global__ void init_deg_kernel(int* deg_out, int* deg_in, int n) {
    int i = blockIdx.x * blockDim.x + threadIdx.x;
    if (i < n) { deg_out[i] = 0; deg_in[i] = 0; }
}

__global__ void count_deg_kernel(const int* __restrict__ src, const int* __restrict__ dst,
                                 int* deg_out, int* deg_in, int e) {
    int i = blockIdx.x * blockDim.x + threadIdx.x;
    if (i < e) {
        atomicAdd(&deg_out[src[i]], 1);
        atomicAdd(&deg_in[dst[i]], 1);
    }
}

__global__ void finalize_deg_kernel(const int* __restrict__ deg_out, const int* __restrict__ deg_in,
                                    float* rs_out, float* rs_in, int n) {
    int i = blockIdx.x * blockDim.x + threadIdx.x;
    if (i < n) {
        rs_out[i] = rsqrtf((float)max(deg_out[i], 1));
        rs_in[i]  = rsqrtf((float)max(deg_in[i], 1));
    }
}

// ---------------- zero kernel ----------------
__global__ void zero_kernel(float4* __restrict__ p, int n4) {
    int i = blockIdx.x * blockDim.x + threadIdx.x;
    int stride = gridDim.x * blockDim.x;
    float4 z = make_float4(0.f, 0.f, 0.f, 0.f);
    for (; i < n4; i += stride) p[i] = z;
}

// ---------------- fused GEMM ----------------
// Y[r, :] = pre(X[r, :]) @ W  (+ post_bias)
// PRE==1: pre = x * rs_a[r]
// PRE==2: pre = relu(x * rs_a[r] + pre_bias[c]) * rs_b[r]
// PRE==3: pre = x * rs_a[r] + pre_bias[c]
template <int N_OUT, int PRE>
__global__ void gemm_kernel(const float* __restrict__ X, const float* __restrict__ W,
                            float* __restrict__ Y, int n_rows,
                            const float* __restrict__ rs_a,
                            const float* __restrict__ rs_b,
                            const float* __restrict__ pre_bias,
                            const float* __restrict__ post_bias) {
    constexpr int K = 128;
    constexpr int TILE_M = 64;
    constexpr int TX = N_OUT / 4;       // threads along N (each does 4 cols)
    constexpr int TY = 256 / TX;        // threads along M
    constexpr int RPT = TILE_M / TY;    // rows per thread

    extern __shared__ float smem[];
    float* Ws = smem;                   // K * N_OUT
    float* Xs = smem + K * N_OUT;       // TILE_M * K

    int tid = threadIdx.x;

    // load W tile (entire K x N_OUT weight)
    const float4* W4 = (const float4*)W;
    float4* Ws4 = (float4*)Ws;
    #pragma unroll 4
    for (int i = tid; i < K * N_OUT / 4; i += 256) Ws4[i] = W4[i];

    int row0 = blockIdx.x * TILE_M;
    int rows = min(TILE_M, n_rows - row0);

    // load X tile with fused pre-op
    const float4* X4 = (const float4*)(X + (size_t)row0 * K);
    float4* Xs4 = (float4*)Xs;
    for (int i = tid; i < rows * (K / 4); i += 256) {
        float4 v = X4[i];
        if (PRE >= 1) {
            int r = i / (K / 4);
            float sa = rs_a[row0 + r];
            if (PRE == 1) {
                v.x *= sa; v.y *= sa; v.z *= sa; v.w *= sa;
            } else {
                int c = (i % (K / 4)) * 4;
                v.x = v.x * sa + pre_bias[c + 0];
                v.y = v.y * sa + pre_bias[c + 1];
                v.z = v.z * sa + pre_bias[c + 2];
                v.w = v.w * sa + pre_bias[c + 3];
                if (PRE == 2) {
                    float sb = rs_b[row0 + r];
                    v.x = fmaxf(v.x, 0.f) * sb;
                    v.y = fmaxf(v.y, 0.f) * sb;
                    v.z = fmaxf(v.z, 0.f) * sb;
                    v.w = fmaxf(v.w, 0.f) * sb;
                }
            }
        }
        Xs4[i] = v;
    }
    __syncthreads();

    int tx = tid % TX;
    int ty = tid / TX;

    float acc[RPT][4];
    #pragma unroll
    for (int i = 0; i < RPT; i++)
        #pragma unroll
        for (int j = 0; j < 4; j++) acc[i][j] = 0.f;

    const float4* WsT = (const float4*)Ws;
    #pragma unroll 8
    for (int k = 0; k < K; k++) {
        float4 w = WsT[k * (N_OUT / 4) + tx];
        #pragma unroll
        for (int i = 0; i < RPT; i++) {
            float a = Xs[(ty * RPT + i) * K + k];
            acc[i][0] = fmaf(a, w.x, acc[i][0]);
            acc[i][1] = fmaf(a, w.y, acc[i][1]);
            acc[i][2] = fmaf(a, w.z, acc[i][2]);
            acc[i][3] = fmaf(a, w.w, acc[i][3]);
        }
    }

    #pragma unroll
    for (int i = 0; i < RPT; i++) {
        int r = ty * RPT + i;
        if (r < rows) {
            float4 o = make_float4(acc[i][0], acc[i][1], acc[i][2], acc[i][3]);
            if (post_bias) {
                int c = tx * 4;
                o.x += post_bias[c + 0];
                o.y += post_bias[c + 1];
                o.z += post_bias[c + 2];
                o.w += post_bias[c + 3];
            }
            *(float4*)(Y + (size_t)(row0 + r) * N_OUT + tx * 4) = o;
        }
    }
}

// ---------------- edge scatter-add ----------------
// Warp processes 32 edges: coalesced index loads, shfl broadcast, float4 gather,
// red.global.add.v4.f32 scatter (no return value -> no scoreboard wait).
__device__ __forceinline__ void red_add_v4(float* p, float4 v) {
    asm volatile("red.global.add.v4.f32 [%0], {%1, %2, %3, %4};"
                 :: "l"(p), "f"(v.x), "f"(v.y), "f"(v.z), "f"(v.w) : "memory");
}

__global__ void scatter_kernel(const float* __restrict__ feat, float* __restrict__ out,
                               const int* __restrict__ src, const int* __restrict__ dst, int e) {
    int lane = threadIdx.x & 31;
    int warp = (blockIdx.x * blockDim.x + threadIdx.x) >> 5;
    int base = warp << 5;
    if (base >= e) return;
    int n = min(32, e - base);
    int s = 0, d = 0;
    if (lane < n) { s = src[base + lane]; d = dst[base + lane]; }

    int i = 0;
    // 4-deep: 4 independent gathers in flight before the reds
    for (; i + 4 <= n; i += 4) {
        int s0 = __shfl_sync(0xffffffffu, s, i + 0);
        int s1 = __shfl_sync(0xffffffffu, s, i + 1);
        int s2 = __shfl_sync(0xffffffffu, s, i + 2);
        int s3 = __shfl_sync(0xffffffffu, s, i + 3);
        int d0 = __shfl_sync(0xffffffffu, d, i + 0);
        int d1 = __shfl_sync(0xffffffffu, d, i + 1);
        int d2 = __shfl_sync(0xffffffffu, d, i + 2);
        int d3 = __shfl_sync(0xffffffffu, d, i + 3);
        float4 v0 = __ldg((const float4*)(feat + (size_t)s0 * FEAT) + lane);
        float4 v1 = __ldg((const float4*)(feat + (size_t)s1 * FEAT) + lane);
        float4 v2 = __ldg((const float4*)(feat + (size_t)s2 * FEAT) + lane);
        float4 v3 = __ldg((const float4*)(feat + (size_t)s3 * FEAT) + lane);
        red_add_v4(out + (size_t)d0 * FEAT + lane * 4, v0);
        red_add_v4(out + (size_t)d1 * FEAT + lane * 4, v1);
        red_add_v4(out + (size_t)d2 * FEAT + lane * 4, v2);
        red_add_v4(out + (size_t)d3 * FEAT + lane * 4, v3);
    }
    for (; i < n; i++) {
        int ss = __shfl_sync(0xffffffffu, s, i);
        int dd = __shfl_sync(0xffffffffu, d, i);
        float4 v = __ldg((const float4*)(feat + (size_t)ss * FEAT) + lane);
        red_add_v4(out + (size_t)dd * FEAT + lane * 4, v);
    }
}

// ---------------- launch ----------------
extern "C" void kernel_launch(void* const* d_in, const int* in_sizes, int n_in,
                              void* d_out, int out_size) {
    const float* in_feat = (const float*)d_in[0];
    const int*   src     = (const int*)d_in[1];
    const int*   dst     = (const int*)d_in[2];
    const float* W1      = (const float*)d_in[3];
    const float* b1      = (const float*)d_in[4];
    const float* W2      = (const float*)d_in[5];
    const float* b2      = (const float*)d_in[6];
    const float* Wf      = (const float*)d_in[7];
    const float* bf      = (const float*)d_in[8];
    float* out = (float*)d_out;

    int n = in_sizes[0] / FEAT;   // 50000
    int e = in_sizes[1];          // 1600000

    float *buf0, *buf1, *rs_out, *rs_in;
    int *dgo, *dgi;
    cudaGetSymbolAddress((void**)&buf0, g_buf0);
    cudaGetSymbolAddress((void**)&buf1, g_buf1);
    cudaGetSymbolAddress((void**)&rs_out, g_rs_out);
    cudaGetSymbolAddress((void**)&rs_in, g_rs_in);
    cudaGetSymbolAddress((void**)&dgo, g_deg_out);
    cudaGetSymbolAddress((void**)&dgi, g_deg_in);

    const int SMEM_128 = (128 * 128 + 64 * 128) * 4;   // 96 KB
    const int SMEM_64  = (128 * 64 + 64 * 128) * 4;    // 64 KB
    cudaFuncSetAttribute(gemm_kernel<128, 1>, cudaFuncAttributeMaxDynamicSharedMemorySize, SMEM_128);
    cudaFuncSetAttribute(gemm_kernel<128, 2>, cudaFuncAttributeMaxDynamicSharedMemorySize, SMEM_128);
    cudaFuncSetAttribute(gemm_kernel<64, 3>,  cudaFuncAttributeMaxDynamicSharedMemorySize, SMEM_64);

    // degrees
    init_deg_kernel<<<(n + 255) / 256, 256>>>(dgo, dgi, n);
    count_deg_kernel<<<(e + 255) / 256, 256>>>(src, dst, dgo, dgi, e);
    finalize_deg_kernel<<<(n + 255) / 256, 256>>>(dgo, dgi, rs_out, rs_in, n);

    int gemm_blocks = (n + 63) / 64;
    int n4 = n * FEAT / 4;
    int scatter_threads = ((e + 31) / 32) * 32;
    int scatter_blocks = (scatter_threads + 255) / 256;

    // layer 1: buf0 = (x * rs_out) @ W1
    gemm_kernel<128, 1><<<gemm_blocks, 256, SMEM_128>>>(in_feat, W1, buf0, n, rs_out, nullptr, nullptr, nullptr);
    zero_kernel<<<1024, 256>>>((float4*)buf1, n4);
    scatter_kernel<<<scatter_blocks, 256>>>(buf0, buf1, src, dst, e);

    // layer 2: buf0 = relu(buf1 * rs_in + b1) * rs_out @ W2
    gemm_kernel<128, 2><<<gemm_blocks, 256, SMEM_128>>>(buf1, W2, buf0, n, rs_in, rs_out, b1, nullptr);
    zero_kernel<<<1024, 256>>>((float4*)buf1, n4);
    scatter_kernel<<<scatter_blocks, 256>>>(buf0, buf1, src, dst, e);

    // final: out = (buf1 * rs_in + b2) @ Wf + bf
    gemm_kernel<64, 3><<<gemm_blocks, 256, SMEM_64>>>(buf1, Wf, out, n, rs_in, nullptr, b2, bf);
}

// round 2
// speedup vs baseline: 1.3352x; 1.3352x over previous
#include <cuda_runtime.h>
#include <cuda_fp16.h>

#define N_NODES 50000
#define FEAT 128
#define E_MAX 1600000

// ---------------- scratch (static device globals; no allocation) ----------------
__device__ __align__(16) float  g_buf0[(size_t)N_NODES * FEAT];       // fp32 aggregation output
__device__ __align__(16) __half g_h16[(size_t)N_NODES * FEAT];        // fp16 GEMM output (gather payload)
__device__ float g_rs_out[N_NODES];
__device__ float g_rs_in[N_NODES];
__device__ int   g_deg_out[N_NODES];
__device__ int   g_deg_in[N_NODES];
__device__ int   g_offsets[N_NODES + 1];
__device__ int   g_cursor[N_NODES];
__device__ int   g_csr_src[E_MAX];

// ---------------- degree kernels ----------------
__global__ void init_deg_kernel(int* deg_out, int* deg_in, int n) {
    int i = blockIdx.x * blockDim.x + threadIdx.x;
    if (i < n) { deg_out[i] = 0; deg_in[i] = 0; }
}

__global__ void count_deg_kernel(const int* __restrict__ src, const int* __restrict__ dst,
                                 int* deg_out, int* deg_in, int e) {
    int i = blockIdx.x * blockDim.x + threadIdx.x;
    if (i < e) {
        atomicAdd(&deg_out[src[i]], 1);
        atomicAdd(&deg_in[dst[i]], 1);
    }
}

__global__ void finalize_deg_kernel(const int* __restrict__ deg_out, const int* __restrict__ deg_in,
                                    float* rs_out, float* rs_in, int n) {
    int i = blockIdx.x * blockDim.x + threadIdx.x;
    if (i < n) {
        rs_out[i] = rsqrtf((float)max(deg_out[i], 1));
        rs_in[i]  = rsqrtf((float)max(deg_in[i], 1));
    }
}

// ---------------- CSR build ----------------
// Single-block exclusive scan of deg_in -> offsets (and cursor copy).
__global__ void scan_kernel(const int* __restrict__ deg, int* offsets, int* cursor, int n) {
    __shared__ int partials[1024];
    int tid = threadIdx.x;
    int C = (n + 1023) / 1024;
    int start = tid * C;
    int end = min(start + C, n);
    int s = 0;
    for (int i = start; i < end; i++) s += deg[i];
    partials[tid] = s;
    __syncthreads();
    if (tid == 0) {
        int acc = 0;
        for (int i = 0; i < 1024; i++) { int t = partials[i]; partials[i] = acc; acc += t; }
    }
    __syncthreads();
    int acc = partials[tid];
    for (int i = start; i < end; i++) {
        offsets[i] = acc;
        cursor[i] = acc;
        acc += deg[i];
    }
    if (tid == 1023) offsets[n] = acc;
}

__global__ void csr_fill_kernel(const int* __restrict__ src, const int* __restrict__ dst,
                                int* cursor, int* __restrict__ csr_src, int e) {
    int i = blockIdx.x * blockDim.x + threadIdx.x;
    if (i < e) {
        int pos = atomicAdd(&cursor[dst[i]], 1);
        csr_src[pos] = src[i];
    }
}

// ---------------- fused GEMM ----------------
// Y[r, :] = pre(X[r, :]) @ W  (+ post_bias)
// PRE==1: pre = x * rs_a[r]
// PRE==2: pre = relu(x * rs_a[r] + pre_bias[c]) * rs_b[r]
// PRE==3: pre = x * rs_a[r] + pre_bias[c]
// HALF_OUT: write __half output (no post_bias path used there)
template <int N_OUT, int PRE, int HALF_OUT>
__global__ void gemm_kernel(const float* __restrict__ X, const float* __restrict__ W,
                            void* __restrict__ Yv, int n_rows,
                            const float* __restrict__ rs_a,
                            const float* __restrict__ rs_b,
                            const float* __restrict__ pre_bias,
                            const float* __restrict__ post_bias) {
    constexpr int K = 128;
    constexpr int TILE_M = 64;
    constexpr int TX = N_OUT / 4;
    constexpr int TY = 256 / TX;
    constexpr int RPT = TILE_M / TY;

    extern __shared__ float smem[];
    float* Ws = smem;                   // K * N_OUT
    float* Xs = smem + K * N_OUT;       // TILE_M * K

    int tid = threadIdx.x;

    const float4* W4 = (const float4*)W;
    float4* Ws4 = (float4*)Ws;
    #pragma unroll 4
    for (int i = tid; i < K * N_OUT / 4; i += 256) Ws4[i] = W4[i];

    int row0 = blockIdx.x * TILE_M;
    int rows = min(TILE_M, n_rows - row0);

    const float4* X4 = (const float4*)(X + (size_t)row0 * K);
    float4* Xs4 = (float4*)Xs;
    for (int i = tid; i < rows * (K / 4); i += 256) {
        float4 v = X4[i];
        int r = i / (K / 4);
        float sa = rs_a[row0 + r];
        if (PRE == 1) {
            v.x *= sa; v.y *= sa; v.z *= sa; v.w *= sa;
        } else {
            int c = (i % (K / 4)) * 4;
            v.x = v.x * sa + pre_bias[c + 0];
            v.y = v.y * sa + pre_bias[c + 1];
            v.z = v.z * sa + pre_bias[c + 2];
            v.w = v.w * sa + pre_bias[c + 3];
            if (PRE == 2) {
                float sb = rs_b[row0 + r];
                v.x = fmaxf(v.x, 0.f) * sb;
                v.y = fmaxf(v.y, 0.f) * sb;
                v.z = fmaxf(v.z, 0.f) * sb;
                v.w = fmaxf(v.w, 0.f) * sb;
            }
        }
        Xs4[i] = v;
    }
    __syncthreads();

    int tx = tid % TX;
    int ty = tid / TX;

    float acc[RPT][4];
    #pragma unroll
    for (int i = 0; i < RPT; i++)
        #pragma unroll
        for (int j = 0; j < 4; j++) acc[i][j] = 0.f;

    const float4* WsT = (const float4*)Ws;
    #pragma unroll 8
    for (int k = 0; k < K; k++) {
        float4 w = WsT[k * (N_OUT / 4) + tx];
        #pragma unroll
        for (int i = 0; i < RPT; i++) {
            float a = Xs[(ty * RPT + i) * K + k];
            acc[i][0] = fmaf(a, w.x, acc[i][0]);
            acc[i][1] = fmaf(a, w.y, acc[i][1]);
            acc[i][2] = fmaf(a, w.z, acc[i][2]);
            acc[i][3] = fmaf(a, w.w, acc[i][3]);
        }
    }

    #pragma unroll
    for (int i = 0; i < RPT; i++) {
        int r = ty * RPT + i;
        if (r < rows) {
            float4 o = make_float4(acc[i][0], acc[i][1], acc[i][2], acc[i][3]);
            if (post_bias) {
                int c = tx * 4;
                o.x += post_bias[c + 0];
                o.y += post_bias[c + 1];
                o.z += post_bias[c + 2];
                o.w += post_bias[c + 3];
            }
            if (HALF_OUT) {
                __half* Yh = (__half*)Yv;
                __half2 p0 = __floats2half2_rn(o.x, o.y);
                __half2 p1 = __floats2half2_rn(o.z, o.w);
                uint2 st;
                st.x = *(unsigned int*)&p0;
                st.y = *(unsigned int*)&p1;
                *(uint2*)(Yh + (size_t)(row0 + r) * N_OUT + tx * 4) = st;
            } else {
                float* Y = (float*)Yv;
                *(float4*)(Y + (size_t)(row0 + r) * N_OUT + tx * 4) = o;
            }
        }
    }
}

// ---------------- CSR gather-aggregate ----------------
// One warp per destination node. Lane handles 4 consecutive features (8 bytes fp16).
// Register accumulation; single fp32 store per node. No atomics.
__device__ __forceinline__ void acc_h(float4& a, uint2 v) {
    __half2 h0 = *(__half2*)&v.x;
    __half2 h1 = *(__half2*)&v.y;
    float2 f0 = __half22float2(h0);
    float2 f1 = __half22float2(h1);
    a.x += f0.x; a.y += f0.y; a.z += f1.x; a.w += f1.y;
}

__global__ void gather_kernel(const __half* __restrict__ feat, float* __restrict__ out,
                              const int* __restrict__ offsets, const int* __restrict__ csr_src,
                              int n) {
    int warp = (blockIdx.x * blockDim.x + threadIdx.x) >> 5;
    if (warp >= n) return;
    int lane = threadIdx.x & 31;
    int beg = offsets[warp];
    int end = offsets[warp + 1];

    const uint2* base = (const uint2*)feat;   // 32 uint2 per 128-half row

    float4 a0 = make_float4(0.f, 0.f, 0.f, 0.f);
    float4 a1 = make_float4(0.f, 0.f, 0.f, 0.f);
    float4 a2 = make_float4(0.f, 0.f, 0.f, 0.f);
    float4 a3 = make_float4(0.f, 0.f, 0.f, 0.f);

    int k = beg;
    for (; k + 4 <= end; k += 4) {
        int s0 = __ldg(csr_src + k + 0);
        int s1 = __ldg(csr_src + k + 1);
        int s2 = __ldg(csr_src + k + 2);
        int s3 = __ldg(csr_src + k + 3);
        uint2 v0 = __ldg(base + (size_t)s0 * 32 + lane);
        uint2 v1 = __ldg(base + (size_t)s1 * 32 + lane);
        uint2 v2 = __ldg(base + (size_t)s2 * 32 + lane);
        uint2 v3 = __ldg(base + (size_t)s3 * 32 + lane);
        acc_h(a0, v0);
        acc_h(a1, v1);
        acc_h(a2, v2);
        acc_h(a3, v3);
    }
    for (; k < end; k++) {
        int s = __ldg(csr_src + k);
        uint2 v = __ldg(base + (size_t)s * 32 + lane);
        acc_h(a0, v);
    }
    a0.x += a1.x + a2.x + a3.x;
    a0.y += a1.y + a2.y + a3.y;
    a0.z += a1.z + a2.z + a3.z;
    a0.w += a1.w + a2.w + a3.w;

    *(float4*)(out + (size_t)warp * FEAT + lane * 4) = a0;
}

// ---------------- launch ----------------
extern "C" void kernel_launch(void* const* d_in, const int* in_sizes, int n_in,
                              void* d_out, int out_size) {
    const float* in_feat = (const float*)d_in[0];
    const int*   src     = (const int*)d_in[1];
    const int*   dst     = (const int*)d_in[2];
    const float* W1      = (const float*)d_in[3];
    const float* b1      = (const float*)d_in[4];
    const float* W2      = (const float*)d_in[5];
    const float* b2      = (const float*)d_in[6];
    const float* Wf      = (const float*)d_in[7];
    const float* bf      = (const float*)d_in[8];
    float* out = (float*)d_out;

    int n = in_sizes[0] / FEAT;   // 50000
    int e = in_sizes[1];          // 1600000

    float *buf0, *rs_out, *rs_in;
    __half* h16;
    int *dgo, *dgi, *offs, *curs, *csrc;
    cudaGetSymbolAddress((void**)&buf0, g_buf0);
    cudaGetSymbolAddress((void**)&h16, g_h16);
    cudaGetSymbolAddress((void**)&rs_out, g_rs_out);
    cudaGetSymbolAddress((void**)&rs_in, g_rs_in);
    cudaGetSymbolAddress((void**)&dgo, g_deg_out);
    cudaGetSymbolAddress((void**)&dgi, g_deg_in);
    cudaGetSymbolAddress((void**)&offs, g_offsets);
    cudaGetSymbolAddress((void**)&curs, g_cursor);
    cudaGetSymbolAddress((void**)&csrc, g_csr_src);

    const int SMEM_128 = (128 * 128 + 64 * 128) * 4;   // 96 KB
    const int SMEM_64  = (128 * 64 + 64 * 128) * 4;    // 64 KB
    cudaFuncSetAttribute(gemm_kernel<128, 1, 1>, cudaFuncAttributeMaxDynamicSharedMemorySize, SMEM_128);
    cudaFuncSetAttribute(gemm_kernel<128, 2, 1>, cudaFuncAttributeMaxDynamicSharedMemorySize, SMEM_128);
    cudaFuncSetAttribute(gemm_kernel<64, 3, 0>,  cudaFuncAttributeMaxDynamicSharedMemorySize, SMEM_64);

    // degrees + CSR build (graph is identical for both layers; build once)
    init_deg_kernel<<<(n + 255) / 256, 256>>>(dgo, dgi, n);
    count_deg_kernel<<<(e + 255) / 256, 256>>>(src, dst, dgo, dgi, e);
    finalize_deg_kernel<<<(n + 255) / 256, 256>>>(dgo, dgi, rs_out, rs_in, n);
    scan_kernel<<<1, 1024>>>(dgi, offs, curs, n);
    csr_fill_kernel<<<(e + 255) / 256, 256>>>(src, dst, curs, csrc, e);

    int gemm_blocks = (n + 63) / 64;
    int gather_blocks = (n * 32 + 255) / 256;

    // layer 1: h16 = (x * rs_out) @ W1   (fp16 output)
    gemm_kernel<128, 1, 1><<<gemm_blocks, 256, SMEM_128>>>(in_feat, W1, h16, n, rs_out, nullptr, nullptr, nullptr);
    gather_kernel<<<gather_blocks, 256>>>(h16, buf0, offs, csrc, n);

    // layer 2: h16 = (relu(buf0 * rs_in + b1) * rs_out) @ W2   (fp16 output)
    gemm_kernel<128, 2, 1><<<gemm_blocks, 256, SMEM_128>>>(buf0, W2, h16, n, rs_in, rs_out, b1, nullptr);
    gather_kernel<<<gather_blocks, 256>>>(h16, buf0, offs, csrc, n);

    // final: out = (buf0 * rs_in + b2) @ Wf + bf   (fp32 output)
    gemm_kernel<64, 3, 0><<<gemm_blocks, 256, SMEM_64>>>(buf0, Wf, out, n, rs_in, nullptr, b2, bf);
}

// round 5
// speedup vs baseline: 2.1748x; 1.6288x over previous
#include <cuda_runtime.h>
#include <cuda_fp16.h>
#include <mma.h>

using namespace nvcuda;

#define N_NODES 50000
#define FEAT 128
#define E_MAX 1600000

// ---------------- scratch (static device globals; no allocation) ----------------
__device__ __align__(16) float  g_buf0[(size_t)N_NODES * FEAT];   // fp32 aggregation output
__device__ __align__(16) __half g_h16[(size_t)N_NODES * FEAT];    // fp16 GEMM output (gather payload)
__device__ float g_rs_out[N_NODES];
__device__ float g_rs_in[N_NODES];
__device__ int   g_deg_out[N_NODES];
__device__ int   g_deg_in[N_NODES];
__device__ int   g_offsets[N_NODES + 1];
__device__ int   g_cursor[N_NODES];
__device__ int   g_csr_src[E_MAX];
__device__ int   g_blocksums[64];

// ---------------- degree kernels ----------------
__global__ void init_deg_kernel(int* deg_out, int* deg_in, int n) {
    int i = blockIdx.x * blockDim.x + threadIdx.x;
    if (i < n) { deg_out[i] = 0; deg_in[i] = 0; }
}

__global__ void count_deg_kernel(const int* __restrict__ src, const int* __restrict__ dst,
                                 int* deg_out, int* deg_in, int e) {
    int i = blockIdx.x * blockDim.x + threadIdx.x;
    if (i < e) {
        atomicAdd(&deg_out[src[i]], 1);
        atomicAdd(&deg_in[dst[i]], 1);
    }
}

__global__ void finalize_deg_kernel(const int* __restrict__ deg_out, const int* __restrict__ deg_in,
                                    float* rs_out, float* rs_in, int n) {
    int i = blockIdx.x * blockDim.x + threadIdx.x;
    if (i < n) {
        rs_out[i] = rsqrtf((float)max(deg_out[i], 1));
        rs_in[i]  = rsqrtf((float)max(deg_in[i], 1));
    }
}

// ---------------- parallel exclusive scan (3 phases) ----------------
__global__ void scan_block_kernel(const int* __restrict__ deg, int* __restrict__ excl,
                                  int* __restrict__ blocksums, int n) {
    int i = blockIdx.x * 1024 + threadIdx.x;
    int v = (i < n) ? deg[i] : 0;
    int lane = threadIdx.x & 31, w = threadIdx.x >> 5;
    int x = v;
    #pragma unroll
    for (int o = 1; o < 32; o <<= 1) {
        int y = __shfl_up_sync(0xffffffffu, x, o);
        if (lane >= o) x += y;
    }
    __shared__ int wt[32];
    if (lane == 31) wt[w] = x;
    __syncthreads();
    if (w == 0) {
        int t = wt[lane];
        #pragma unroll
        for (int o = 1; o < 32; o <<= 1) {
            int y = __shfl_up_sync(0xffffffffu, t, o);
            if (lane >= o) t += y;
        }
        wt[lane] = t;
    }
    __syncthreads();
    int base = (w > 0) ? wt[w - 1] : 0;
    int incl = base + x;
    if (i < n) excl[i] = incl - v;
    if (threadIdx.x == 1023) blocksums[blockIdx.x] = incl;
}

__global__ void scan_sums_kernel(int* bs, int nb) {
    int tid = threadIdx.x;              // 64 threads, nb <= 64
    int v = (tid < nb) ? bs[tid] : 0;
    int lane = tid & 31, w = tid >> 5;
    int x = v;
    #pragma unroll
    for (int o = 1; o < 32; o <<= 1) {
        int y = __shfl_up_sync(0xffffffffu, x, o);
        if (lane >= o) x += y;
    }
    __shared__ int wt[2];
    if (lane == 31) wt[w] = x;
    __syncthreads();
    int base = (w == 1) ? wt[0] : 0;
    int incl = base + x;
    if (tid < nb) bs[tid] = incl - v;   // exclusive
}

__global__ void scan_add_kernel(int* __restrict__ offsets, const int* __restrict__ bs,
                                int* __restrict__ cursor, int n, int e) {
    int i = blockIdx.x * 1024 + threadIdx.x;
    if (i < n) {
        int o = offsets[i] + bs[blockIdx.x];
        offsets[i] = o;
        cursor[i] = o;
    }
    if (blockIdx.x == 0 && threadIdx.x == 0) offsets[n] = e;
}

__global__ void csr_fill_kernel(const int* __restrict__ src, const int* __restrict__ dst,
                                int* cursor, int* __restrict__ csr_src, int e) {
    int i = blockIdx.x * blockDim.x + threadIdx.x;
    if (i < e) {
        int pos = atomicAdd(&cursor[dst[i]], 1);
        csr_src[pos] = src[i];
    }
}

// ---------------- fused tensor-core GEMM (wmma fp16 in, fp32 acc) ----------------
// Y[r,:] = pre(X[r,:]) @ W  (+ post_bias)
// PRE==1: x * rs_a[r]
// PRE==2: relu(x * rs_a[r] + pre_bias[c]) * rs_b[r]
// PRE==3: x * rs_a[r] + pre_bias[c]
template <int N_OUT, int PRE, int HALF_OUT>
__global__ void gemm_tc_kernel(const float* __restrict__ X, const float* __restrict__ W,
                               void* __restrict__ Yv, int n_rows,
                               const float* __restrict__ rs_a,
                               const float* __restrict__ rs_b,
                               const float* __restrict__ pre_bias,
                               const float* __restrict__ post_bias) {
    constexpr int K = 128;
    constexpr int TILE_M = 64;
    constexpr int LDW = N_OUT + 8;       // halves
    constexpr int LDX = K + 8;           // halves
    constexpr int LDY = N_OUT + 4;       // floats
    constexpr int NF = (N_OUT / 2) / 16; // acc frags per warp (4 or 2)

    extern __shared__ char smem_raw[];
    __half* Ws = (__half*)smem_raw;                       // K x LDW
    __half* Xs = (__half*)(smem_raw + K * LDW * 2);       // TILE_M x LDX
    float*  Ys = (float*)smem_raw;                        // TILE_M x LDY (reused)

    int tid = threadIdx.x;
    int row0 = blockIdx.x * TILE_M;
    int rows = min(TILE_M, n_rows - row0);

    // --- load W (K x N_OUT fp32 row-major) -> fp16 smem ---
    const float4* W4 = (const float4*)W;
    for (int i = tid; i < K * (N_OUT / 4); i += 256) {
        int k = i / (N_OUT / 4);
        int c = (i % (N_OUT / 4)) * 4;
        float4 v = W4[i];
        __half2 p0 = __floats2half2_rn(v.x, v.y);
        __half2 p1 = __floats2half2_rn(v.z, v.w);
        uint2 st; st.x = *(unsigned int*)&p0; st.y = *(unsigned int*)&p1;
        *(uint2*)(Ws + k * LDW + c) = st;
    }

    // --- zero pad rows of Xs (last block) ---
    if (rows < TILE_M) {
        int n_half = (TILE_M - rows) * LDX;
        __half* base = Xs + rows * LDX;
        for (int i = tid; i < n_half; i += 256) base[i] = __ushort_as_half(0);
    }

    // --- load X tile with fused pre-op -> fp16 smem ---
    const float4* X4 = (const float4*)(X + (size_t)row0 * K);
    for (int i = tid; i < rows * (K / 4); i += 256) {
        float4 v = X4[i];
        int r = i / (K / 4);
        int c = (i % (K / 4)) * 4;
        float sa = rs_a[row0 + r];
        if (PRE == 1) {
            v.x *= sa; v.y *= sa; v.z *= sa; v.w *= sa;
        } else {
            v.x = v.x * sa + pre_bias[c + 0];
            v.y = v.y * sa + pre_bias[c + 1];
            v.z = v.z * sa + pre_bias[c + 2];
            v.w = v.w * sa + pre_bias[c + 3];
            if (PRE == 2) {
                float sb = rs_b[row0 + r];
                v.x = fmaxf(v.x, 0.f) * sb;
                v.y = fmaxf(v.y, 0.f) * sb;
                v.z = fmaxf(v.z, 0.f) * sb;
                v.w = fmaxf(v.w, 0.f) * sb;
            }
        }
        __half2 p0 = __floats2half2_rn(v.x, v.y);
        __half2 p1 = __floats2half2_rn(v.z, v.w);
        uint2 st; st.x = *(unsigned int*)&p0; st.y = *(unsigned int*)&p1;
        *(uint2*)(Xs + r * LDX + c) = st;
    }
    __syncthreads();

    // --- compute: 8 warps, warp tile = 16 x (N_OUT/2) ---
    int warp = tid >> 5;
    int warp_m = warp >> 1;              // 0..3
    int warp_n = warp & 1;               // 0..1

    wmma::fragment<wmma::accumulator, 16, 16, 16, float> acc[NF];
    #pragma unroll
    for (int j = 0; j < NF; j++) wmma::fill_fragment(acc[j], 0.0f);

    wmma::fragment<wmma::matrix_a, 16, 16, 16, __half, wmma::row_major> a_frag;
    wmma::fragment<wmma::matrix_b, 16, 16, 16, __half, wmma::row_major> b_frag;

    #pragma unroll
    for (int k = 0; k < K / 16; k++) {
        wmma::load_matrix_sync(a_frag, Xs + (warp_m * 16) * LDX + k * 16, LDX);
        #pragma unroll
        for (int j = 0; j < NF; j++) {
            wmma::load_matrix_sync(b_frag, Ws + (k * 16) * LDW + warp_n * (N_OUT / 2) + j * 16, LDW);
            wmma::mma_sync(acc[j], a_frag, b_frag, acc[j]);
        }
    }
    __syncthreads();   // all smem reads done before Ys overwrites Ws/Xs

    #pragma unroll
    for (int j = 0; j < NF; j++) {
        wmma::store_matrix_sync(Ys + (warp_m * 16) * LDY + warp_n * (N_OUT / 2) + j * 16,
                                acc[j], LDY, wmma::mem_row_major);
    }
    __syncthreads();

    // --- epilogue: bias + convert + store ---
    for (int i = tid; i < rows * (N_OUT / 4); i += 256) {
        int r = i / (N_OUT / 4);
        int c = (i % (N_OUT / 4)) * 4;
        float4 o = *(float4*)(Ys + r * LDY + c);
        if (post_bias) {
            o.x += post_bias[c + 0];
            o.y += post_bias[c + 1];
            o.z += post_bias[c + 2];
            o.w += post_bias[c + 3];
        }
        if (HALF_OUT) {
            __half* Yh = (__half*)Yv;
            __half2 p0 = __floats2half2_rn(o.x, o.y);
            __half2 p1 = __floats2half2_rn(o.z, o.w);
            uint2 st; st.x = *(unsigned int*)&p0; st.y = *(unsigned int*)&p1;
            *(uint2*)(Yh + (size_t)(row0 + r) * N_OUT + c) = st;
        } else {
            *(float4*)((float*)Yv + (size_t)(row0 + r) * N_OUT + c) = o;
        }
    }
}

// ---------------- CSR gather-aggregate ----------------
__device__ __forceinline__ void acc_h(float4& a, uint2 v) {
    __half2 h0 = *(__half2*)&v.x;
    __half2 h1 = *(__half2*)&v.y;
    float2 f0 = __half22float2(h0);
    float2 f1 = __half22float2(h1);
    a.x += f0.x; a.y += f0.y; a.z += f1.x; a.w += f1.y;
}

__global__ void gather_kernel(const __half* __restrict__ feat, float* __restrict__ out,
                              const int* __restrict__ offsets, const int* __restrict__ csr_src,
                              int n) {
    int warp = (blockIdx.x * blockDim.x + threadIdx.x) >> 5;
    if (warp >= n) return;
    int lane = threadIdx.x & 31;
    int beg = offsets[warp];
    int end = offsets[warp + 1];

    const uint2* base = (const uint2*)feat;

    float4 a0 = make_float4(0.f, 0.f, 0.f, 0.f);
    float4 a1 = make_float4(0.f, 0.f, 0.f, 0.f);
    float4 a2 = make_float4(0.f, 0.f, 0.f, 0.f);
    float4 a3 = make_float4(0.f, 0.f, 0.f, 0.f);

    int k = beg;
    for (; k + 4 <= end; k += 4) {
        int s0 = __ldg(csr_src + k + 0);
        int s1 = __ldg(csr_src + k + 1);
        int s2 = __ldg(csr_src + k + 2);
        int s3 = __ldg(csr_src + k + 3);
        uint2 v0 = __ldg(base + (size_t)s0 * 32 + lane);
        uint2 v1 = __ldg(base + (size_t)s1 * 32 + lane);
        uint2 v2 = __ldg(base + (size_t)s2 * 32 + lane);
        uint2 v3 = __ldg(base + (size_t)s3 * 32 + lane);
        acc_h(a0, v0);
        acc_h(a1, v1);
        acc_h(a2, v2);
        acc_h(a3, v3);
    }
    for (; k < end; k++) {
        int s = __ldg(csr_src + k);
        uint2 v = __ldg(base + (size_t)s * 32 + lane);
        acc_h(a0, v);
    }
    a0.x += a1.x + a2.x + a3.x;
    a0.y += a1.y + a2.y + a3.y;
    a0.z += a1.z + a2.z + a3.z;
    a0.w += a1.w + a2.w + a3.w;

    *(float4*)(out + (size_t)warp * FEAT + lane * 4) = a0;
}

// ---------------- launch ----------------
extern "C" void kernel_launch(void* const* d_in, const int* in_sizes, int n_in,
                              void* d_out, int out_size) {
    const float* in_feat = (const float*)d_in[0];
    const int*   src     = (const int*)d_in[1];
    const int*   dst     = (const int*)d_in[2];
    const float* W1      = (const float*)d_in[3];
    const float* b1      = (const float*)d_in[4];
    const float* W2      = (const float*)d_in[5];
    const float* b2      = (const float*)d_in[6];
    const float* Wf      = (const float*)d_in[7];
    const float* bf      = (const float*)d_in[8];
    float* out = (float*)d_out;

    int n = in_sizes[0] / FEAT;   // 50000
    int e = in_sizes[1];          // 1600000

    float *buf0, *rs_out, *rs_in;
    __half* h16;
    int *dgo, *dgi, *offs, *curs, *csrc, *bsum;
    cudaGetSymbolAddress((void**)&buf0, g_buf0);
    cudaGetSymbolAddress((void**)&h16, g_h16);
    cudaGetSymbolAddress((void**)&rs_out, g_rs_out);
    cudaGetSymbolAddress((void**)&rs_in, g_rs_in);
    cudaGetSymbolAddress((void**)&dgo, g_deg_out);
    cudaGetSymbolAddress((void**)&dgi, g_deg_in);
    cudaGetSymbolAddress((void**)&offs, g_offsets);
    cudaGetSymbolAddress((void**)&curs, g_cursor);
    cudaGetSymbolAddress((void**)&csrc, g_csr_src);
    cudaGetSymbolAddress((void**)&bsum, g_blocksums);

    // dyn smem: N_OUT=128: max(128*136*2 + 64*136*2, 64*132*4) = 52224
    //           N_OUT=64 : max(128*72*2 + 64*136*2, 64*68*4)  = 35840
    const int SMEM_128 = 128 * 136 * 2 + 64 * 136 * 2;
    const int SMEM_64  = 128 * 72 * 2 + 64 * 136 * 2;
    cudaFuncSetAttribute(gemm_tc_kernel<128, 1, 1>, cudaFuncAttributeMaxDynamicSharedMemorySize, SMEM_128);
    cudaFuncSetAttribute(gemm_tc_kernel<128, 2, 1>, cudaFuncAttributeMaxDynamicSharedMemorySize, SMEM_128);
    cudaFuncSetAttribute(gemm_tc_kernel<64, 3, 0>,  cudaFuncAttributeMaxDynamicSharedMemorySize, SMEM_64);

    // degrees + CSR build (graph identical for both layers; build once)
    init_deg_kernel<<<(n + 255) / 256, 256>>>(dgo, dgi, n);
    count_deg_kernel<<<(e + 255) / 256, 256>>>(src, dst, dgo, dgi, e);
    finalize_deg_kernel<<<(n + 255) / 256, 256>>>(dgo, dgi, rs_out, rs_in, n);

    int nscan_blocks = (n + 1023) / 1024;   // 49
    scan_block_kernel<<<nscan_blocks, 1024>>>(dgi, offs, bsum, n);
    scan_sums_kernel<<<1, 64>>>(bsum, nscan_blocks);
    scan_add_kernel<<<nscan_blocks, 1024>>>(offs, bsum, curs, n, e);
    csr_fill_kernel<<<(e + 255) / 256, 256>>>(src, dst, curs, csrc, e);

    int gemm_blocks = (n + 63) / 64;
    int gather_blocks = (n * 32 + 255) / 256;

    // layer 1: h16 = (x * rs_out) @ W1
    gemm_tc_kernel<128, 1, 1><<<gemm_blocks, 256, SMEM_128>>>(in_feat, W1, h16, n, rs_out, nullptr, nullptr, nullptr);
    gather_kernel<<<gather_blocks, 256>>>(h16, buf0, offs, csrc, n);

    // layer 2: h16 = (relu(buf0 * rs_in + b1) * rs_out) @ W2
    gemm_tc_kernel<128, 2, 1><<<gemm_blocks, 256, SMEM_128>>>(buf0, W2, h16, n, rs_in, rs_out, b1, nullptr);
    gather_kernel<<<gather_blocks, 256>>>(h16, buf0, offs, csrc, n);

    // final: out = (buf0 * rs_in + b2) @ Wf + bf
    gemm_tc_kernel<64, 3, 0><<<gemm_blocks, 256, SMEM_64>>>(buf0, Wf, out, n, rs_in, nullptr, b2, bf);
}